// round 13
// baseline (speedup 1.0000x reference)
#include <cuda_runtime.h>
#include <cuda_fp16.h>
#include <math.h>
#include <cstdint>

#define B_   2
#define T_   2048
#define DM   2048
#define NH   16
#define HD   128
#define HP_  8
#define QKV_N 6144
#define CN   8192
#define LAMBDA_INIT  0.7008206670670481f
#define ONE_MINUS_LI 0.2991793329329519f
#define QSCL (0.08838834764831845f * 1.44269504088896340f)

// ---------------- scratch ----------------
__device__ float g_C[(size_t)B_ * T_ * CN];
__device__ __half g_Qh[(size_t)B_ * NH * T_ * HD];
__device__ __half g_Kh[(size_t)B_ * NH * T_ * HD];
__device__ __half g_Vth[(size_t)B_ * HP_ * 256 * T_];
__device__ float g_Y[(size_t)B_ * NH * T_ * 256];
__device__ float g_lam[HP_];
__device__ __half g_Xhi[(size_t)B_ * T_ * DM];
__device__ __half g_Xlo[(size_t)B_ * T_ * DM];
__device__ __half g_WT[(size_t)CN * DM];
__device__ float g_cos[(size_t)T_ * 64];
__device__ float g_sin[(size_t)T_ * 64];

// ================= helpers =================
__device__ __forceinline__ uint32_t smem_u32(const void* p) {
    uint32_t a;
    asm("{ .reg .u64 t; cvta.to.shared.u64 t, %1; cvt.u32.u64 %0, t; }" : "=r"(a) : "l"(p));
    return a;
}
#define CP_ASYNC16(dst, src) \
    asm volatile("cp.async.cg.shared.global [%0], [%1], 16;" :: "r"(dst), "l"(src) : "memory")
#define CP_COMMIT() asm volatile("cp.async.commit_group;" ::: "memory")
#define CP_WAIT0()  asm volatile("cp.async.wait_group 0;" ::: "memory")
#define CP_WAIT1()  asm volatile("cp.async.wait_group 1;" ::: "memory")
#define CP_WAIT2()  asm volatile("cp.async.wait_group 2;" ::: "memory")
#define EX2F(d, s)     asm("ex2.approx.f32 %0, %1;" : "=f"(d) : "f"(s))
#define LDMX4(r, addr) \
    asm volatile("ldmatrix.sync.aligned.m8n8.x4.shared.b16 {%0,%1,%2,%3}, [%4];" \
        : "=r"((r)[0]), "=r"((r)[1]), "=r"((r)[2]), "=r"((r)[3]) : "r"(addr))

__device__ __forceinline__ void mma_f16(float* c, const uint32_t* a, uint32_t b0, uint32_t b1) {
    asm volatile(
        "mma.sync.aligned.m16n8k16.row.col.f32.f16.f16.f32 "
        "{%0,%1,%2,%3}, {%4,%5,%6,%7}, {%8,%9}, {%0,%1,%2,%3};"
        : "+f"(c[0]), "+f"(c[1]), "+f"(c[2]), "+f"(c[3])
        : "r"(a[0]), "r"(a[1]), "r"(a[2]), "r"(a[3]), "r"(b0), "r"(b1));
}

// ================= f16 GEMM + fused qkv epilogue =================
#define GBM 128
#define GBN 128
#define APB 80
#define A_SB (128 * APB)
#define STAGE_B (3 * A_SB)
#define GEMM_SMEM (3 * STAGE_B)

__device__ __forceinline__ void gemm_stage_load(const __half* __restrict__ Ahi,
                                                const __half* __restrict__ Alo,
                                                const __half* __restrict__ Bt,
                                                int K, int m0, int n0, int kt,
                                                uint32_t sbase, int tid, bool lo) {
#pragma unroll
    for (int i = 0; i < 2; i++) {
        int c = tid + i * 256;
        int r = c >> 2, c16 = c & 3;
        uint32_t off = (uint32_t)(r * APB + c16 * 16);
        size_t ga = (size_t)(m0 + r) * K + kt * 32 + c16 * 8;
        size_t gb = (size_t)(n0 + r) * K + kt * 32 + c16 * 8;
        CP_ASYNC16(sbase + off,              Ahi + ga);
        if (lo) CP_ASYNC16(sbase + A_SB + off, Alo + ga);
        CP_ASYNC16(sbase + 2 * A_SB + off,   Bt + gb);
    }
    CP_COMMIT();
}

__global__ void __launch_bounds__(256, 2) gemm_f16_kernel(const __half* __restrict__ Ahi,
                                                          const __half* __restrict__ Alo,
                                                          const __half* __restrict__ Bt,
                                                          float* __restrict__ C,
                                                          int N, int K) {
    extern __shared__ char smraw[];
    uint32_t sm_b = smem_u32(smraw);
    float* sf = (float*)smraw;
    const int tid = threadIdx.x;
    const int wid = tid >> 5;
    const int lane = tid & 31;
    const int warpM = wid & 1;
    const int warpN = wid >> 1;
    const int m0 = blockIdx.y * GBM;
    const int n0 = (gridDim.x - 1 - blockIdx.x) * GBN;
    const bool lo = (n0 >= QKV_N);
    const int NT = K / 32;
    const int lr = lane >> 2;
    const int lc = lane & 3;
    const int lm_row = lane & 15;
    const int lm_hi  = (lane >> 4) * 16;

    float acc[4][4][4];
#pragma unroll
    for (int i = 0; i < 4; i++)
#pragma unroll
        for (int j = 0; j < 4; j++)
#pragma unroll
            for (int u = 0; u < 4; u++) acc[i][j][u] = 0.0f;

    gemm_stage_load(Ahi, Alo, Bt, K, m0, n0, 0, sm_b, tid, lo);
    gemm_stage_load(Ahi, Alo, Bt, K, m0, n0, 1, sm_b + STAGE_B, tid, lo);

    int buf = 0;
    for (int kt = 0; kt < NT; kt++) {
        if (kt + 1 < NT) { CP_WAIT1(); } else { CP_WAIT0(); }
        __syncthreads();
        if (kt + 2 < NT) {
            int nbuf = buf + 2; if (nbuf >= 3) nbuf -= 3;
            gemm_stage_load(Ahi, Alo, Bt, K, m0, n0, kt + 2,
                            sm_b + (uint32_t)(nbuf * STAGE_B), tid, lo);
        }

        uint32_t sA = sm_b + (uint32_t)(buf * STAGE_B);
        uint32_t a_base = sA + (uint32_t)((warpM * 64 + lm_row) * APB + lm_hi);
        uint32_t b_base = sA + 2u * A_SB + (uint32_t)((warpN * 32 + lm_row) * APB + lm_hi);

#pragma unroll
        for (int half = 0; half < 2; half++) {
            uint32_t hb = (uint32_t)(half * 32);
            uint32_t bh[2][4];
#pragma unroll
            for (int nb = 0; nb < 2; nb++)
                LDMX4(bh[nb], b_base + (uint32_t)(nb * 16 * APB) + hb);
#pragma unroll
            for (int ma = 0; ma < 4; ma++) {
                uint32_t ah[4], al[4];
                uint32_t addr = a_base + (uint32_t)(ma * 16 * APB) + hb;
                LDMX4(ah, addr);
                if (lo) LDMX4(al, addr + A_SB);
#pragma unroll
                for (int na = 0; na < 4; na++) {
                    int nb = na >> 1, j = na & 1;
                    mma_f16(acc[ma][na], ah, bh[nb][j], bh[nb][j + 2]);
                }
                if (lo) {
#pragma unroll
                    for (int na = 0; na < 4; na++) {
                        int nb = na >> 1, j = na & 1;
                        mma_f16(acc[ma][na], al, bh[nb][j], bh[nb][j + 2]);
                    }
                }
            }
        }
        buf++; if (buf == 3) buf = 0;
    }

    if (lo) {
#pragma unroll
        for (int ma = 0; ma < 4; ma++) {
            int r0 = m0 + warpM * 64 + ma * 16 + lr;
#pragma unroll
            for (int na = 0; na < 4; na++) {
                int c0 = n0 + warpN * 32 + na * 8 + lc * 2;
                *(float2*)(C + (size_t)r0 * N + c0)       = make_float2(acc[ma][na][0], acc[ma][na][1]);
                *(float2*)(C + (size_t)(r0 + 8) * N + c0) = make_float2(acc[ma][na][2], acc[ma][na][3]);
            }
        }
        return;
    }

    // ---- fused qkv epilogue ----
    __syncthreads();
#pragma unroll
    for (int ma = 0; ma < 4; ma++) {
        int r = warpM * 64 + ma * 16 + lr;
#pragma unroll
        for (int na = 0; na < 4; na++) {
            int c = warpN * 32 + na * 8 + lc * 2;
            *(float2*)(sf + r * 132 + c)       = make_float2(acc[ma][na][0], acc[ma][na][1]);
            *(float2*)(sf + (r + 8) * 132 + c) = make_float2(acc[ma][na][2], acc[ma][na][3]);
        }
    }
    __syncthreads();

    const int tile3 = (n0 >> 7) % 3;
    const int h = n0 / 384;
    const int bb = m0 / T_;
    const int t0 = m0 % T_;

    if (tile3 == 2) {
        int c = tid >> 1, rh = (tid & 1) * 64;
        int e = ((h & 1) << 7) + c;
        __half* dst = g_Vth + ((size_t)(bb * HP_ + (h >> 1)) * 256 + e) * T_ + t0 + rh;
#pragma unroll
        for (int r8 = 0; r8 < 64; r8 += 8) {
            __half2 p[4];
#pragma unroll
            for (int j = 0; j < 4; j++) {
                float a  = sf[(rh + r8 + 2 * j)     * 132 + c];
                float b2 = sf[(rh + r8 + 2 * j + 1) * 132 + c];
                p[j] = __halves2half2(__float2half_rn(a), __float2half_rn(b2));
            }
            *(uint4*)(dst + r8) = *(uint4*)p;
        }
    } else {
        int r = tid >> 1, half = tid & 1;
        const float* row = sf + r * 132;
        float ss = 0.0f;
#pragma unroll 8
        for (int i = 0; i < 64; i++) {
            float v = row[half * 64 + i];
            ss += v * v;
        }
        ss += __shfl_xor_sync(0xffffffffu, ss, 1);
        float rq = rsqrtf(ss * (1.0f / 128.0f) + 1e-6f);
        if (tile3 == 0) rq *= QSCL;
        int t = t0 + r;
        const float* ctab = g_cos + (size_t)t * 64;
        const float* stab = g_sin + (size_t)t * 64;
        __half* dst = ((tile3 == 0) ? g_Qh : g_Kh)
                      + ((size_t)(bb * NH + h) * T_ + t) * HD + half * 64;
#pragma unroll
        for (int i8 = 0; i8 < 64; i8 += 8) {
            __half2 p[4];
#pragma unroll
            for (int j = 0; j < 4; j++) {
                float o2[2];
#pragma unroll
                for (int u = 0; u < 2; u++) {
                    int i = i8 + 2 * j + u;
                    float cs = ctab[i], sn = stab[i];
                    float xa = row[i] * rq, xb = row[i + 64] * rq;
                    o2[u] = half ? (-xa * sn + xb * cs) : (xa * cs + xb * sn);
                }
                p[j] = __halves2half2(__float2half_rn(o2[0]), __float2half_rn(o2[1]));
            }
            *(uint4*)(dst + i8) = *(uint4*)p;
        }
    }
}

// ================= pre-kernels =================
__global__ void rope_tab_kernel() {
    int t = blockIdx.x, i = threadIdx.x;
    float invf = expf(-(float)i * (9.210340371976184f / 64.0f));
    float fr = (float)t * invf;
    g_cos[(size_t)t * 64 + i] = cosf(fr);
    g_sin[(size_t)t * 64 + i] = sinf(fr);
}

__global__ void splitx_f16_kernel(const float* __restrict__ x,
                                  __half* __restrict__ xhi,
                                  __half* __restrict__ xlo, int n4) {
    int i = blockIdx.x * blockDim.x + threadIdx.x;
    if (i < n4) {
        float4 v = ((const float4*)x)[i];
        float f[4] = {v.x, v.y, v.z, v.w};
        __half h[4], l[4];
#pragma unroll
        for (int j = 0; j < 4; j++) {
            h[j] = __float2half_rn(f[j]);
            l[j] = __float2half_rn(f[j] - __half2float(h[j]));
        }
        ((uint2*)xhi)[i] = *(uint2*)h;
        ((uint2*)xlo)[i] = *(uint2*)l;
    }
}

__global__ void wt_f16_kernel(const float* __restrict__ W,
                              __half* __restrict__ WT,
                              int K, int Nc, int nrow_off) {
    __shared__ float tile[32][33];
    int n0 = blockIdx.x * 32, k0 = blockIdx.y * 32;
    int tx = threadIdx.x, ty = threadIdx.y;
#pragma unroll
    for (int i = 0; i < 4; i++)
        tile[ty + i * 8][tx] = W[(size_t)(k0 + ty + i * 8) * Nc + n0 + tx];
    __syncthreads();
#pragma unroll
    for (int i = 0; i < 4; i++) {
        float v = tile[tx][ty + i * 8];
        WT[(size_t)(nrow_off + n0 + ty + i * 8) * K + k0 + tx] = __float2half_rn(v);
    }
}

// ---------------- lambda ----------------
__global__ void lam_kernel(const float* __restrict__ lq1, const float* __restrict__ lk1,
                           const float* __restrict__ lq2, const float* __restrict__ lk2) {
    int hp = threadIdx.y;
    int lane = threadIdx.x;
    float s1 = lq1[hp*64 + lane] * lk1[hp*64 + lane] + lq1[hp*64 + lane + 32] * lk1[hp*64 + lane + 32];
    float s2 = lq2[hp*64 + lane] * lk2[hp*64 + lane] + lq2[hp*64 + lane + 32] * lk2[hp*64 + lane + 32];
#pragma unroll
    for (int off = 16; off > 0; off >>= 1) {
        s1 += __shfl_xor_sync(0xffffffffu, s1, off);
        s2 += __shfl_xor_sync(0xffffffffu, s2, off);
    }
    if (lane == 0) g_lam[hp] = expf(s1) - expf(s2) + LAMBDA_INIT;
}

// ---------------- flash attention: Q-tile 128, warp-private rows ----------------
#define QS_B   0
#define KS0_B  34816
#define KS1_B  52224
#define VT_B   69632
#define PS_B   106496
#define ATT_SMEM 124928

__global__ void __launch_bounds__(256, 1) attn_kernel() {
    const int mt = gridDim.x - 1 - blockIdx.x;
    const int h = blockIdx.y, b = blockIdx.z;
    const int tid = threadIdx.x, wid = tid >> 5, lane = tid & 31;
    const int lr = lane >> 2, lc = lane & 3;
    const int rw = wid * 16;          // warp's row base (16 rows per warp, 128 total)
    const int lm_row = lane & 15;
    const int lm_hi  = (lane >> 4) * 16;

    extern __shared__ char smc[];
    uint32_t smb = smem_u32(smc);

    const __half* Qg  = g_Qh  + ((size_t)(b * NH + h) * T_ + (size_t)mt * 128) * HD;
    const __half* Kg  = g_Kh  + (size_t)(b * NH + h) * T_ * HD;
    const __half* Vtg = g_Vth + (size_t)(b * HP_ + (h >> 1)) * 256 * T_;
    float*        Yg  = g_Y   + (size_t)(b * NH + h) * T_ * 256;

    // prologue: K(0) 64x128, Q 128x128
#pragma unroll
    for (int i = 0; i < 4; i++) {
        int idx = tid + i * 256;
        int r = idx >> 4, c16 = idx & 15;
        CP_ASYNC16(smb + (uint32_t)(KS0_B + r * 272 + c16 * 16),
                   Kg + (size_t)r * HD + c16 * 8);
    }
    CP_COMMIT();
#pragma unroll
    for (int i = 0; i < 8; i++) {
        int idx = tid + i * 256;
        int r = idx >> 4, c16 = idx & 15;
        CP_ASYNC16(smb + (uint32_t)(QS_B + r * 272 + c16 * 16),
                   Qg + (size_t)r * HD + c16 * 8);
    }
    CP_COMMIT();

    float O[32][4];
#pragma unroll
    for (int i = 0; i < 32; i++)
#pragma unroll
        for (int j = 0; j < 4; j++) O[i][j] = 0.0f;
    float m0 = -1e30f, m1 = -1e30f, l0 = 0.0f, l1 = 0.0f;

    const uint32_t qs_base  = smb + (uint32_t)(QS_B  + (rw + lm_row) * 272 + lm_hi);
    const uint32_t ks_base0 = smb + (uint32_t)(KS0_B + lm_row * 272 + lm_hi);
    const uint32_t ks_base1 = smb + (uint32_t)(KS1_B + lm_row * 272 + lm_hi);
    const uint32_t ps_base  = smb + (uint32_t)(PS_B  + (rw + lm_row) * 144 + lm_hi);
    const uint32_t vt_base  = smb + (uint32_t)(VT_B  + lm_row * 144 + lm_hi);

    const int ntmax = 2 * mt + 1;
    for (int nt = 0; nt <= ntmax; nt++) {
        __syncthreads();
        // V(nt): 256e x 64t
#pragma unroll
        for (int i = 0; i < 8; i++) {
            int idx = tid + i * 256;
            int r = idx >> 3, c = idx & 7;
            CP_ASYNC16(smb + (uint32_t)(VT_B + r * 144 + c * 16),
                       Vtg + (size_t)r * T_ + nt * 64 + c * 8);
        }
        CP_COMMIT();
        if (nt < ntmax) {
            int koff = ((nt + 1) & 1) ? KS1_B : KS0_B;
#pragma unroll
            for (int i = 0; i < 4; i++) {
                int idx = tid + i * 256;
                int r = idx >> 4, c16 = idx & 15;
                CP_ASYNC16(smb + (uint32_t)(koff + r * 272 + c16 * 16),
                           Kg + (size_t)((nt + 1) * 64 + r) * HD + c16 * 8);
            }
            CP_COMMIT();
        }
        if (nt < ntmax) { CP_WAIT2(); } else { CP_WAIT1(); }
        __syncthreads();

        // ---- S = Q K^T : warp owns 16 rows x 64 cols ----
        uint32_t kb_base = (nt & 1) ? ks_base1 : ks_base0;
        float accS[8][4];
#pragma unroll
        for (int na = 0; na < 8; na++)
#pragma unroll
            for (int u = 0; u < 4; u++) accS[na][u] = 0.0f;
#pragma unroll
        for (int ks = 0; ks < 8; ks++) {
            uint32_t ah[4];
            LDMX4(ah, qs_base + ks * 32u);
#pragma unroll
            for (int pr = 0; pr < 4; pr++) {
                uint32_t kb[4];
                LDMX4(kb, kb_base + (uint32_t)(pr * 16 * 272) + ks * 32u);
                mma_f16(accS[pr * 2],     ah, kb[0], kb[2]);
                mma_f16(accS[pr * 2 + 1], ah, kb[1], kb[3]);
            }
        }

        // ---- causal mask (last two K-tiles only) ----
        if (nt >= 2 * mt) {
            int rg0 = mt * 128 + rw + lr;
#pragma unroll
            for (int na = 0; na < 8; na++) {
                int colg = nt * 64 + na * 8 + 2 * lc;
                if (colg     > rg0)     accS[na][0] = -1e30f;
                if (colg + 1 > rg0)     accS[na][1] = -1e30f;
                if (colg     > rg0 + 8) accS[na][2] = -1e30f;
                if (colg + 1 > rg0 + 8) accS[na][3] = -1e30f;
            }
        }

        // ---- warp-local online softmax ----
        float mx0 = -1e30f, mx1 = -1e30f;
#pragma unroll
        for (int na = 0; na < 8; na++) {
            mx0 = fmaxf(mx0, fmaxf(accS[na][0], accS[na][1]));
            mx1 = fmaxf(mx1, fmaxf(accS[na][2], accS[na][3]));
        }
        mx0 = fmaxf(mx0, __shfl_xor_sync(0xffffffffu, mx0, 1));
        mx0 = fmaxf(mx0, __shfl_xor_sync(0xffffffffu, mx0, 2));
        mx1 = fmaxf(mx1, __shfl_xor_sync(0xffffffffu, mx1, 1));
        mx1 = fmaxf(mx1, __shfl_xor_sync(0xffffffffu, mx1, 2));
        float mn0 = fmaxf(m0, mx0);
        float mn1 = fmaxf(m1, mx1);
        float a0, a1;
        EX2F(a0, m0 - mn0);
        EX2F(a1, m1 - mn1);
        float s0 = 0.0f, s1 = 0.0f;
#pragma unroll
        for (int na = 0; na < 8; na++) {
            float p00, p01, p10, p11;
            EX2F(p00, accS[na][0] - mn0);
            EX2F(p01, accS[na][1] - mn0);
            EX2F(p10, accS[na][2] - mn1);
            EX2F(p11, accS[na][3] - mn1);
            __half hp00 = __float2half_rn(p00), hp01 = __float2half_rn(p01);
            __half hp10 = __float2half_rn(p10), hp11 = __float2half_rn(p11);
            s0 += __half2float(hp00) + __half2float(hp01);
            s1 += __half2float(hp10) + __half2float(hp11);
            int col = na * 8 + 2 * lc;
            *(__half2*)(smc + PS_B + (rw + lr) * 144 + col * 2)     = __halves2half2(hp00, hp01);
            *(__half2*)(smc + PS_B + (rw + lr + 8) * 144 + col * 2) = __halves2half2(hp10, hp11);
        }
        s0 += __shfl_xor_sync(0xffffffffu, s0, 1);
        s0 += __shfl_xor_sync(0xffffffffu, s0, 2);
        s1 += __shfl_xor_sync(0xffffffffu, s1, 1);
        s1 += __shfl_xor_sync(0xffffffffu, s1, 2);
        l0 = l0 * a0 + s0;
        l1 = l1 * a1 + s1;
        m0 = mn0; m1 = mn1;
        __syncwarp();
#pragma unroll
        for (int i = 0; i < 32; i++) {
            O[i][0] *= a0; O[i][1] *= a0; O[i][2] *= a1; O[i][3] *= a1;
        }

        // wait V(nt), then CTA barrier (all threads' V chunks visible)
        if (nt < ntmax) { CP_WAIT1(); } else { CP_WAIT0(); }
        __syncthreads();

        // ---- O += P @ V : 16 rows x 256 e per warp ----
#pragma unroll
        for (int ks = 0; ks < 4; ks++) {
            uint32_t pf[4];
            LDMX4(pf, ps_base + ks * 32u);
#pragma unroll
            for (int pr = 0; pr < 16; pr++) {
                uint32_t vb[4];
                LDMX4(vb, vt_base + (uint32_t)(pr * 16 * 144) + ks * 32u);
                mma_f16(O[pr * 2],     pf, vb[0], vb[2]);
                mma_f16(O[pr * 2 + 1], pf, vb[1], vb[3]);
            }
        }
    }

    // epilogue
    float i0, i1;
    asm("rcp.approx.f32 %0, %1;" : "=f"(i0) : "f"(l0));
    asm("rcp.approx.f32 %0, %1;" : "=f"(i1) : "f"(l1));
    int tg0 = mt * 128 + rw + lr;
#pragma unroll
    for (int na = 0; na < 32; na++) {
        int col = na * 8 + 2 * lc;
        *(float2*)(Yg + (size_t)tg0 * 256 + col)       = make_float2(O[na][0] * i0, O[na][1] * i0);
        *(float2*)(Yg + (size_t)(tg0 + 8) * 256 + col) = make_float2(O[na][2] * i1, O[na][3] * i1);
    }
}

// ---------------- combine ----------------
__global__ void combine_kernel(float* __restrict__ out) {
    int t = blockIdx.x, hp = blockIdx.y, b = blockIdx.z;
    int e = threadIdx.x;
    size_t y1i = ((size_t)(b * NH + 2 * hp)     * T_ + t) * 256 + e;
    size_t y2i = ((size_t)(b * NH + 2 * hp + 1) * T_ + t) * 256 + e;
    float y1 = g_Y[y1i], y2 = g_Y[y2i];
    float lam = g_lam[hp];
    float gv = g_C[((size_t)(b * T_ + t)) * CN + QKV_N + hp * 256 + e];
    float sg = gv / (1.0f + expf(-gv));
    float yv = (y1 - lam * y2) * sg;

    __shared__ float red[8];
    float s = yv * yv;
#pragma unroll
    for (int off = 16; off > 0; off >>= 1)
        s += __shfl_xor_sync(0xffffffffu, s, off);
    if ((e & 31) == 0) red[e >> 5] = s;
    __syncthreads();
    float tot = 0.0f;
#pragma unroll
    for (int w = 0; w < 8; w++) tot += red[w];
    float r = rsqrtf(tot * (1.0f / 256.0f) + 1e-6f) * ONE_MINUS_LI;
    out[((size_t)(b * T_ + t)) * DM + hp * 256 + e] = yv * r;
}

// ---------------- launch ----------------
extern "C" void kernel_launch(void* const* d_in, const int* in_sizes, int n_in,
                              void* d_out, int out_size) {
    const float* x    = (const float*)d_in[0];
    const float* Wqkv = (const float*)d_in[1];
    const float* lq1  = (const float*)d_in[2];
    const float* lk1  = (const float*)d_in[3];
    const float* lq2  = (const float*)d_in[4];
    const float* lk2  = (const float*)d_in[5];
    const float* Wg   = (const float*)d_in[6];
    float* out = (float*)d_out;

    float *c_p;
    __half *xhi_p, *xlo_p, *wt_p;
    cudaGetSymbolAddress((void**)&c_p,   g_C);
    cudaGetSymbolAddress((void**)&xhi_p, g_Xhi);
    cudaGetSymbolAddress((void**)&xlo_p, g_Xlo);
    cudaGetSymbolAddress((void**)&wt_p,  g_WT);

    rope_tab_kernel<<<T_, 64>>>();
    int nx4 = B_ * T_ * DM / 4;
    splitx_f16_kernel<<<(nx4 + 255) / 256, 256>>>(x, xhi_p, xlo_p, nx4);
    wt_f16_kernel<<<dim3(QKV_N / 32, DM / 32), dim3(32, 8)>>>(Wqkv, wt_p, DM, QKV_N, 0);
    wt_f16_kernel<<<dim3(DM / 32,    DM / 32), dim3(32, 8)>>>(Wg,   wt_p, DM, DM, QKV_N);

    cudaFuncSetAttribute(gemm_f16_kernel, cudaFuncAttributeMaxDynamicSharedMemorySize, GEMM_SMEM);
    gemm_f16_kernel<<<dim3(CN / GBN, (B_ * T_) / GBM), 256, GEMM_SMEM>>>(xhi_p, xlo_p, wt_p, c_p, CN, DM);

    lam_kernel<<<1, dim3(32, 8)>>>(lq1, lk1, lq2, lk2);
    cudaFuncSetAttribute(attn_kernel, cudaFuncAttributeMaxDynamicSharedMemorySize, ATT_SMEM);
    attn_kernel<<<dim3(T_ / 128, NH, B_), 256, ATT_SMEM>>>();
    combine_kernel<<<dim3(T_, HP_, B_), 256>>>(out);
}

// round 14
// speedup vs baseline: 1.2723x; 1.2723x over previous
#include <cuda_runtime.h>
#include <cuda_fp16.h>
#include <math.h>
#include <cstdint>

#define B_   2
#define T_   2048
#define DM   2048
#define NH   16
#define HD   128
#define HP_  8
#define QKV_N 6144
#define CN   8192
#define LAMBDA_INIT  0.7008206670670481f
#define ONE_MINUS_LI 0.2991793329329519f
#define QSCL (0.08838834764831845f * 1.44269504088896340f)

// ---------------- scratch ----------------
__device__ float g_C[(size_t)B_ * T_ * CN];
__device__ __half g_Qh[(size_t)B_ * NH * T_ * HD];
__device__ __half g_Kh[(size_t)B_ * NH * T_ * HD];
__device__ __half g_Vth[(size_t)B_ * HP_ * 256 * T_];
__device__ float g_Y[(size_t)B_ * NH * T_ * 256];
__device__ float g_lam[HP_];
__device__ __half g_Xh[(size_t)B_ * T_ * DM];
__device__ __half g_WT[(size_t)CN * DM];
__device__ float g_cos[(size_t)T_ * 64];
__device__ float g_sin[(size_t)T_ * 64];

// ================= helpers =================
__device__ __forceinline__ uint32_t smem_u32(const void* p) {
    uint32_t a;
    asm("{ .reg .u64 t; cvta.to.shared.u64 t, %1; cvt.u32.u64 %0, t; }" : "=r"(a) : "l"(p));
    return a;
}
#define CP_ASYNC16(dst, src) \
    asm volatile("cp.async.cg.shared.global [%0], [%1], 16;" :: "r"(dst), "l"(src) : "memory")
#define CP_COMMIT() asm volatile("cp.async.commit_group;" ::: "memory")
#define CP_WAIT0()  asm volatile("cp.async.wait_group 0;" ::: "memory")
#define CP_WAIT1()  asm volatile("cp.async.wait_group 1;" ::: "memory")
#define CP_WAIT2()  asm volatile("cp.async.wait_group 2;" ::: "memory")
#define EX2F(d, s)     asm("ex2.approx.f32 %0, %1;" : "=f"(d) : "f"(s))
#define LDMX4(r, addr) \
    asm volatile("ldmatrix.sync.aligned.m8n8.x4.shared.b16 {%0,%1,%2,%3}, [%4];" \
        : "=r"((r)[0]), "=r"((r)[1]), "=r"((r)[2]), "=r"((r)[3]) : "r"(addr))

__device__ __forceinline__ void mma_f16(float* c, const uint32_t* a, uint32_t b0, uint32_t b1) {
    asm volatile(
        "mma.sync.aligned.m16n8k16.row.col.f32.f16.f16.f32 "
        "{%0,%1,%2,%3}, {%4,%5,%6,%7}, {%8,%9}, {%0,%1,%2,%3};"
        : "+f"(c[0]), "+f"(c[1]), "+f"(c[2]), "+f"(c[3])
        : "r"(a[0]), "r"(a[1]), "r"(a[2]), "r"(a[3]), "r"(b0), "r"(b1));
}

// ================= f16 GEMM (single-mma everywhere) + fused qkv epilogue =================
#define GBM 128
#define GBN 128
#define APB 80
#define A_SB (128 * APB)             // 10240 B
#define STAGE_B (2 * A_SB)           // 20480 B (A, B)
#define GEMM_SMEM 67584              // max(3 stages = 61440, epilogue staging 128*132*4)

__device__ __forceinline__ void gemm_stage_load(const __half* __restrict__ Ah,
                                                const __half* __restrict__ Bt,
                                                int K, int m0, int n0, int kt,
                                                uint32_t sbase, int tid) {
#pragma unroll
    for (int i = 0; i < 2; i++) {
        int c = tid + i * 256;
        int r = c >> 2, c16 = c & 3;
        uint32_t off = (uint32_t)(r * APB + c16 * 16);
        CP_ASYNC16(sbase + off,        Ah + (size_t)(m0 + r) * K + kt * 32 + c16 * 8);
        CP_ASYNC16(sbase + A_SB + off, Bt + (size_t)(n0 + r) * K + kt * 32 + c16 * 8);
    }
    CP_COMMIT();
}

__global__ void __launch_bounds__(256, 2) gemm_f16_kernel(const __half* __restrict__ Ah,
                                                          const __half* __restrict__ Bt,
                                                          float* __restrict__ C,
                                                          int N, int K) {
    extern __shared__ char smraw[];
    uint32_t sm_b = smem_u32(smraw);
    float* sf = (float*)smraw;
    const int tid = threadIdx.x;
    const int wid = tid >> 5;
    const int lane = tid & 31;
    const int warpM = wid & 1;
    const int warpN = wid >> 1;
    const int m0 = blockIdx.y * GBM;
    const int n0 = blockIdx.x * GBN;
    const int NT = K / 32;
    const int lr = lane >> 2;
    const int lc = lane & 3;
    const int lm_row = lane & 15;
    const int lm_hi  = (lane >> 4) * 16;

    float acc[4][4][4];
#pragma unroll
    for (int i = 0; i < 4; i++)
#pragma unroll
        for (int j = 0; j < 4; j++)
#pragma unroll
            for (int u = 0; u < 4; u++) acc[i][j][u] = 0.0f;

    gemm_stage_load(Ah, Bt, K, m0, n0, 0, sm_b, tid);
    gemm_stage_load(Ah, Bt, K, m0, n0, 1, sm_b + STAGE_B, tid);

    int buf = 0;
    for (int kt = 0; kt < NT; kt++) {
        if (kt + 1 < NT) { CP_WAIT1(); } else { CP_WAIT0(); }
        __syncthreads();
        if (kt + 2 < NT) {
            int nbuf = buf + 2; if (nbuf >= 3) nbuf -= 3;
            gemm_stage_load(Ah, Bt, K, m0, n0, kt + 2,
                            sm_b + (uint32_t)(nbuf * STAGE_B), tid);
        }

        uint32_t sA = sm_b + (uint32_t)(buf * STAGE_B);
        uint32_t a_base = sA + (uint32_t)((warpM * 64 + lm_row) * APB + lm_hi);
        uint32_t b_base = sA + A_SB + (uint32_t)((warpN * 32 + lm_row) * APB + lm_hi);

#pragma unroll
        for (int half = 0; half < 2; half++) {
            uint32_t hb = (uint32_t)(half * 32);
            uint32_t bh[2][4];
#pragma unroll
            for (int nb = 0; nb < 2; nb++)
                LDMX4(bh[nb], b_base + (uint32_t)(nb * 16 * APB) + hb);
#pragma unroll
            for (int ma = 0; ma < 4; ma++) {
                uint32_t ah[4];
                LDMX4(ah, a_base + (uint32_t)(ma * 16 * APB) + hb);
#pragma unroll
                for (int na = 0; na < 4; na++) {
                    int nb = na >> 1, j = na & 1;
                    mma_f16(acc[ma][na], ah, bh[nb][j], bh[nb][j + 2]);
                }
            }
        }
        buf++; if (buf == 3) buf = 0;
    }

    if (n0 >= QKV_N) {
        // gate tiles: fp32 store to g_C
#pragma unroll
        for (int ma = 0; ma < 4; ma++) {
            int r0 = m0 + warpM * 64 + ma * 16 + lr;
#pragma unroll
            for (int na = 0; na < 4; na++) {
                int c0 = n0 + warpN * 32 + na * 8 + lc * 2;
                *(float2*)(C + (size_t)r0 * N + c0)       = make_float2(acc[ma][na][0], acc[ma][na][1]);
                *(float2*)(C + (size_t)(r0 + 8) * N + c0) = make_float2(acc[ma][na][2], acc[ma][na][3]);
            }
        }
        return;
    }

    // ---- fused qkv epilogue ----
    __syncthreads();
#pragma unroll
    for (int ma = 0; ma < 4; ma++) {
        int r = warpM * 64 + ma * 16 + lr;
#pragma unroll
        for (int na = 0; na < 4; na++) {
            int c = warpN * 32 + na * 8 + lc * 2;
            *(float2*)(sf + r * 132 + c)       = make_float2(acc[ma][na][0], acc[ma][na][1]);
            *(float2*)(sf + (r + 8) * 132 + c) = make_float2(acc[ma][na][2], acc[ma][na][3]);
        }
    }
    __syncthreads();

    const int tile3 = (n0 >> 7) % 3;
    const int h = n0 / 384;
    const int bb = m0 / T_;
    const int t0 = m0 % T_;

    if (tile3 == 2) {
        int c = tid >> 1, rh = (tid & 1) * 64;
        int e = ((h & 1) << 7) + c;
        __half* dst = g_Vth + ((size_t)(bb * HP_ + (h >> 1)) * 256 + e) * T_ + t0 + rh;
#pragma unroll
        for (int r8 = 0; r8 < 64; r8 += 8) {
            __half2 p[4];
#pragma unroll
            for (int j = 0; j < 4; j++) {
                float a  = sf[(rh + r8 + 2 * j)     * 132 + c];
                float b2 = sf[(rh + r8 + 2 * j + 1) * 132 + c];
                p[j] = __halves2half2(__float2half_rn(a), __float2half_rn(b2));
            }
            *(uint4*)(dst + r8) = *(uint4*)p;
        }
    } else {
        int r = tid >> 1, half = tid & 1;
        const float* row = sf + r * 132;
        float ss = 0.0f;
#pragma unroll 8
        for (int i = 0; i < 64; i++) {
            float v = row[half * 64 + i];
            ss += v * v;
        }
        ss += __shfl_xor_sync(0xffffffffu, ss, 1);
        float rq = rsqrtf(ss * (1.0f / 128.0f) + 1e-6f);
        if (tile3 == 0) rq *= QSCL;
        int t = t0 + r;
        const float* ctab = g_cos + (size_t)t * 64;
        const float* stab = g_sin + (size_t)t * 64;
        __half* dst = ((tile3 == 0) ? g_Qh : g_Kh)
                      + ((size_t)(bb * NH + h) * T_ + t) * HD + half * 64;
#pragma unroll
        for (int i8 = 0; i8 < 64; i8 += 8) {
            __half2 p[4];
#pragma unroll
            for (int j = 0; j < 4; j++) {
                float o2[2];
#pragma unroll
                for (int u = 0; u < 2; u++) {
                    int i = i8 + 2 * j + u;
                    float cs = ctab[i], sn = stab[i];
                    float xa = row[i] * rq, xb = row[i + 64] * rq;
                    o2[u] = half ? (-xa * sn + xb * cs) : (xa * cs + xb * sn);
                }
                p[j] = __halves2half2(__float2half_rn(o2[0]), __float2half_rn(o2[1]));
            }
            *(uint4*)(dst + i8) = *(uint4*)p;
        }
    }
}

// ================= pre-kernels =================
__global__ void rope_tab_kernel() {
    int t = blockIdx.x, i = threadIdx.x;
    float invf = expf(-(float)i * (9.210340371976184f / 64.0f));
    float fr = (float)t * invf;
    g_cos[(size_t)t * 64 + i] = cosf(fr);
    g_sin[(size_t)t * 64 + i] = sinf(fr);
}

__global__ void roundx_f16_kernel(const float* __restrict__ x,
                                  __half* __restrict__ xh, int n4) {
    int i = blockIdx.x * blockDim.x + threadIdx.x;
    if (i < n4) {
        float4 v = ((const float4*)x)[i];
        __half h[4];
        h[0] = __float2half_rn(v.x);
        h[1] = __float2half_rn(v.y);
        h[2] = __float2half_rn(v.z);
        h[3] = __float2half_rn(v.w);
        ((uint2*)xh)[i] = *(uint2*)h;
    }
}

__global__ void wt_f16_kernel(const float* __restrict__ W,
                              __half* __restrict__ WT,
                              int K, int Nc, int nrow_off) {
    __shared__ float tile[32][33];
    int n0 = blockIdx.x * 32, k0 = blockIdx.y * 32;
    int tx = threadIdx.x, ty = threadIdx.y;
#pragma unroll
    for (int i = 0; i < 4; i++)
        tile[ty + i * 8][tx] = W[(size_t)(k0 + ty + i * 8) * Nc + n0 + tx];
    __syncthreads();
#pragma unroll
    for (int i = 0; i < 4; i++) {
        float v = tile[tx][ty + i * 8];
        WT[(size_t)(nrow_off + n0 + ty + i * 8) * K + k0 + tx] = __float2half_rn(v);
    }
}

// ---------------- lambda ----------------
__global__ void lam_kernel(const float* __restrict__ lq1, const float* __restrict__ lk1,
                           const float* __restrict__ lq2, const float* __restrict__ lk2) {
    int hp = threadIdx.y;
    int lane = threadIdx.x;
    float s1 = lq1[hp*64 + lane] * lk1[hp*64 + lane] + lq1[hp*64 + lane + 32] * lk1[hp*64 + lane + 32];
    float s2 = lq2[hp*64 + lane] * lk2[hp*64 + lane] + lq2[hp*64 + lane + 32] * lk2[hp*64 + lane + 32];
#pragma unroll
    for (int off = 16; off > 0; off >>= 1) {
        s1 += __shfl_xor_sync(0xffffffffu, s1, off);
        s2 += __shfl_xor_sync(0xffffffffu, s2, off);
    }
    if (lane == 0) g_lam[hp] = expf(s1) - expf(s2) + LAMBDA_INIT;
}

// ---------------- flash attention: Q-tile 128, warp-private rows ----------------
#define QS_B   0
#define KS0_B  34816
#define KS1_B  52224
#define VT_B   69632
#define PS_B   106496
#define ATT_SMEM 124928

__global__ void __launch_bounds__(256, 1) attn_kernel() {
    const int mt = gridDim.x - 1 - blockIdx.x;
    const int h = blockIdx.y, b = blockIdx.z;
    const int tid = threadIdx.x, wid = tid >> 5, lane = tid & 31;
    const int lr = lane >> 2, lc = lane & 3;
    const int rw = wid * 16;
    const int lm_row = lane & 15;
    const int lm_hi  = (lane >> 4) * 16;

    extern __shared__ char smc[];
    uint32_t smb = smem_u32(smc);

    const __half* Qg  = g_Qh  + ((size_t)(b * NH + h) * T_ + (size_t)mt * 128) * HD;
    const __half* Kg  = g_Kh  + (size_t)(b * NH + h) * T_ * HD;
    const __half* Vtg = g_Vth + (size_t)(b * HP_ + (h >> 1)) * 256 * T_;
    float*        Yg  = g_Y   + (size_t)(b * NH + h) * T_ * 256;

#pragma unroll
    for (int i = 0; i < 4; i++) {
        int idx = tid + i * 256;
        int r = idx >> 4, c16 = idx & 15;
        CP_ASYNC16(smb + (uint32_t)(KS0_B + r * 272 + c16 * 16),
                   Kg + (size_t)r * HD + c16 * 8);
    }
    CP_COMMIT();
#pragma unroll
    for (int i = 0; i < 8; i++) {
        int idx = tid + i * 256;
        int r = idx >> 4, c16 = idx & 15;
        CP_ASYNC16(smb + (uint32_t)(QS_B + r * 272 + c16 * 16),
                   Qg + (size_t)r * HD + c16 * 8);
    }
    CP_COMMIT();

    float O[32][4];
#pragma unroll
    for (int i = 0; i < 32; i++)
#pragma unroll
        for (int j = 0; j < 4; j++) O[i][j] = 0.0f;
    float m0 = -1e30f, m1 = -1e30f, l0 = 0.0f, l1 = 0.0f;

    const uint32_t qs_base  = smb + (uint32_t)(QS_B  + (rw + lm_row) * 272 + lm_hi);
    const uint32_t ks_base0 = smb + (uint32_t)(KS0_B + lm_row * 272 + lm_hi);
    const uint32_t ks_base1 = smb + (uint32_t)(KS1_B + lm_row * 272 + lm_hi);
    const uint32_t ps_base  = smb + (uint32_t)(PS_B  + (rw + lm_row) * 144 + lm_hi);
    const uint32_t vt_base  = smb + (uint32_t)(VT_B  + lm_row * 144 + lm_hi);

    const int ntmax = 2 * mt + 1;
    for (int nt = 0; nt <= ntmax; nt++) {
        __syncthreads();
#pragma unroll
        for (int i = 0; i < 8; i++) {
            int idx = tid + i * 256;
            int r = idx >> 3, c = idx & 7;
            CP_ASYNC16(smb + (uint32_t)(VT_B + r * 144 + c * 16),
                       Vtg + (size_t)r * T_ + nt * 64 + c * 8);
        }
        CP_COMMIT();
        if (nt < ntmax) {
            int koff = ((nt + 1) & 1) ? KS1_B : KS0_B;
#pragma unroll
            for (int i = 0; i < 4; i++) {
                int idx = tid + i * 256;
                int r = idx >> 4, c16 = idx & 15;
                CP_ASYNC16(smb + (uint32_t)(koff + r * 272 + c16 * 16),
                           Kg + (size_t)((nt + 1) * 64 + r) * HD + c16 * 8);
            }
            CP_COMMIT();
        }
        if (nt < ntmax) { CP_WAIT2(); } else { CP_WAIT1(); }
        __syncthreads();

        uint32_t kb_base = (nt & 1) ? ks_base1 : ks_base0;
        float accS[8][4];
#pragma unroll
        for (int na = 0; na < 8; na++)
#pragma unroll
            for (int u = 0; u < 4; u++) accS[na][u] = 0.0f;
#pragma unroll
        for (int ks = 0; ks < 8; ks++) {
            uint32_t ah[4];
            LDMX4(ah, qs_base + ks * 32u);
#pragma unroll
            for (int pr = 0; pr < 4; pr++) {
                uint32_t kb[4];
                LDMX4(kb, kb_base + (uint32_t)(pr * 16 * 272) + ks * 32u);
                mma_f16(accS[pr * 2],     ah, kb[0], kb[2]);
                mma_f16(accS[pr * 2 + 1], ah, kb[1], kb[3]);
            }
        }

        if (nt >= 2 * mt) {
            int rg0 = mt * 128 + rw + lr;
#pragma unroll
            for (int na = 0; na < 8; na++) {
                int colg = nt * 64 + na * 8 + 2 * lc;
                if (colg     > rg0)     accS[na][0] = -1e30f;
                if (colg + 1 > rg0)     accS[na][1] = -1e30f;
                if (colg     > rg0 + 8) accS[na][2] = -1e30f;
                if (colg + 1 > rg0 + 8) accS[na][3] = -1e30f;
            }
        }

        float mx0 = -1e30f, mx1 = -1e30f;
#pragma unroll
        for (int na = 0; na < 8; na++) {
            mx0 = fmaxf(mx0, fmaxf(accS[na][0], accS[na][1]));
            mx1 = fmaxf(mx1, fmaxf(accS[na][2], accS[na][3]));
        }
        mx0 = fmaxf(mx0, __shfl_xor_sync(0xffffffffu, mx0, 1));
        mx0 = fmaxf(mx0, __shfl_xor_sync(0xffffffffu, mx0, 2));
        mx1 = fmaxf(mx1, __shfl_xor_sync(0xffffffffu, mx1, 1));
        mx1 = fmaxf(mx1, __shfl_xor_sync(0xffffffffu, mx1, 2));
        float mn0 = fmaxf(m0, mx0);
        float mn1 = fmaxf(m1, mx1);
        float a0, a1;
        EX2F(a0, m0 - mn0);
        EX2F(a1, m1 - mn1);
        float s0 = 0.0f, s1 = 0.0f;
#pragma unroll
        for (int na = 0; na < 8; na++) {
            float p00, p01, p10, p11;
            EX2F(p00, accS[na][0] - mn0);
            EX2F(p01, accS[na][1] - mn0);
            EX2F(p10, accS[na][2] - mn1);
            EX2F(p11, accS[na][3] - mn1);
            __half hp00 = __float2half_rn(p00), hp01 = __float2half_rn(p01);
            __half hp10 = __float2half_rn(p10), hp11 = __float2half_rn(p11);
            s0 += __half2float(hp00) + __half2float(hp01);
            s1 += __half2float(hp10) + __half2float(hp11);
            int col = na * 8 + 2 * lc;
            *(__half2*)(smc + PS_B + (rw + lr) * 144 + col * 2)     = __halves2half2(hp00, hp01);
            *(__half2*)(smc + PS_B + (rw + lr + 8) * 144 + col * 2) = __halves2half2(hp10, hp11);
        }
        s0 += __shfl_xor_sync(0xffffffffu, s0, 1);
        s0 += __shfl_xor_sync(0xffffffffu, s0, 2);
        s1 += __shfl_xor_sync(0xffffffffu, s1, 1);
        s1 += __shfl_xor_sync(0xffffffffu, s1, 2);
        l0 = l0 * a0 + s0;
        l1 = l1 * a1 + s1;
        m0 = mn0; m1 = mn1;
        __syncwarp();
#pragma unroll
        for (int i = 0; i < 32; i++) {
            O[i][0] *= a0; O[i][1] *= a0; O[i][2] *= a1; O[i][3] *= a1;
        }

        if (nt < ntmax) { CP_WAIT1(); } else { CP_WAIT0(); }
        __syncthreads();

#pragma unroll
        for (int ks = 0; ks < 4; ks++) {
            uint32_t pf[4];
            LDMX4(pf, ps_base + ks * 32u);
#pragma unroll
            for (int pr = 0; pr < 16; pr++) {
                uint32_t vb[4];
                LDMX4(vb, vt_base + (uint32_t)(pr * 16 * 144) + ks * 32u);
                mma_f16(O[pr * 2],     pf, vb[0], vb[2]);
                mma_f16(O[pr * 2 + 1], pf, vb[1], vb[3]);
            }
        }
    }

    float i0, i1;
    asm("rcp.approx.f32 %0, %1;" : "=f"(i0) : "f"(l0));
    asm("rcp.approx.f32 %0, %1;" : "=f"(i1) : "f"(l1));
    int tg0 = mt * 128 + rw + lr;
#pragma unroll
    for (int na = 0; na < 32; na++) {
        int col = na * 8 + 2 * lc;
        *(float2*)(Yg + (size_t)tg0 * 256 + col)       = make_float2(O[na][0] * i0, O[na][1] * i0);
        *(float2*)(Yg + (size_t)(tg0 + 8) * 256 + col) = make_float2(O[na][2] * i1, O[na][3] * i1);
    }
}

// ---------------- combine ----------------
__global__ void combine_kernel(float* __restrict__ out) {
    int t = blockIdx.x, hp = blockIdx.y, b = blockIdx.z;
    int e = threadIdx.x;
    size_t y1i = ((size_t)(b * NH + 2 * hp)     * T_ + t) * 256 + e;
    size_t y2i = ((size_t)(b * NH + 2 * hp + 1) * T_ + t) * 256 + e;
    float y1 = g_Y[y1i], y2 = g_Y[y2i];
    float lam = g_lam[hp];
    float gv = g_C[((size_t)(b * T_ + t)) * CN + QKV_N + hp * 256 + e];
    float sg = gv / (1.0f + expf(-gv));
    float yv = (y1 - lam * y2) * sg;

    __shared__ float red[8];
    float s = yv * yv;
#pragma unroll
    for (int off = 16; off > 0; off >>= 1)
        s += __shfl_xor_sync(0xffffffffu, s, off);
    if ((e & 31) == 0) red[e >> 5] = s;
    __syncthreads();
    float tot = 0.0f;
#pragma unroll
    for (int w = 0; w < 8; w++) tot += red[w];
    float r = rsqrtf(tot * (1.0f / 256.0f) + 1e-6f) * ONE_MINUS_LI;
    out[((size_t)(b * T_ + t)) * DM + hp * 256 + e] = yv * r;
}

// ---------------- launch ----------------
extern "C" void kernel_launch(void* const* d_in, const int* in_sizes, int n_in,
                              void* d_out, int out_size) {
    const float* x    = (const float*)d_in[0];
    const float* Wqkv = (const float*)d_in[1];
    const float* lq1  = (const float*)d_in[2];
    const float* lk1  = (const float*)d_in[3];
    const float* lq2  = (const float*)d_in[4];
    const float* lk2  = (const float*)d_in[5];
    const float* Wg   = (const float*)d_in[6];
    float* out = (float*)d_out;

    float *c_p;
    __half *xh_p, *wt_p;
    cudaGetSymbolAddress((void**)&c_p,  g_C);
    cudaGetSymbolAddress((void**)&xh_p, g_Xh);
    cudaGetSymbolAddress((void**)&wt_p, g_WT);

    rope_tab_kernel<<<T_, 64>>>();
    int nx4 = B_ * T_ * DM / 4;
    roundx_f16_kernel<<<(nx4 + 255) / 256, 256>>>(x, xh_p, nx4);
    wt_f16_kernel<<<dim3(QKV_N / 32, DM / 32), dim3(32, 8)>>>(Wqkv, wt_p, DM, QKV_N, 0);
    wt_f16_kernel<<<dim3(DM / 32,    DM / 32), dim3(32, 8)>>>(Wg,   wt_p, DM, DM, QKV_N);

    cudaFuncSetAttribute(gemm_f16_kernel, cudaFuncAttributeMaxDynamicSharedMemorySize, GEMM_SMEM);
    gemm_f16_kernel<<<dim3(CN / GBN, (B_ * T_) / GBM), 256, GEMM_SMEM>>>(xh_p, wt_p, c_p, CN, DM);

    lam_kernel<<<1, dim3(32, 8)>>>(lq1, lk1, lq2, lk2);
    cudaFuncSetAttribute(attn_kernel, cudaFuncAttributeMaxDynamicSharedMemorySize, ATT_SMEM);
    attn_kernel<<<dim3(T_ / 128, NH, B_), 256, ATT_SMEM>>>();
    combine_kernel<<<dim3(T_, HP_, B_), 256>>>(out);
}